// round 15
// baseline (speedup 1.0000x reference)
#include <cuda_runtime.h>
#include <math_constants.h>
#include <cstdint>

#define NN 50000
#define NE 800000
#define NEE 850000          // NE + NN self loops
#define DD 128
#define HH 4
#define NB 25               // scan blocks (2048 elems each)

// ---- scratch (device globals; no allocations allowed) ----
__device__ float g_xl[NN * DD];
__device__ float g_xr[NN * DD];
__device__ float g_res[NN * DD];
__device__ float g_h[NN * DD];       // tf32-rounded at write (feeds gemm only)
__device__ float g_xcvt[NN * DD];    // tf32-rounded copy of external x
__device__ float g_wcvt[6 * DD * DD];// tf32-rounded weights
__device__ int   g_rowptr[NN + 1];
__device__ int   g_cnt[NN];          // zero at module load; re-zeroed by scan23
__device__ int   g_off[NN];
__device__ int   g_csrc[NEE];
__device__ int   g_bsum[32];

__device__ __forceinline__ unsigned f2tf32(float x) {
    unsigned u;
    asm("cvt.rna.tf32.f32 %0, %1;" : "=r"(u) : "f"(x));
    return u;
}
__device__ __forceinline__ float tf32r(float x) {
    return __uint_as_float(f2tf32(x));
}

// ============ fused: tf32 pre-convert (x + weights) AND dst histogram ============
#define NX4 (NN * DD / 4)        // 1,600,000 float4
#define NW4 (6 * DD * DD / 4)    // 24,576 float4
#define CVT_JOBS (NX4 + NW4)

__global__ void cvt_hist_kernel(const float4* __restrict__ x,
                                const float4* __restrict__ w0, const float4* __restrict__ w1,
                                const float4* __restrict__ w2, const float4* __restrict__ w3,
                                const float4* __restrict__ w4, const float4* __restrict__ w5,
                                const int* __restrict__ ei) {
    int i = blockIdx.x * blockDim.x + threadIdx.x;
    if (i < NX4) {
        float4 v = x[i];
        v.x = tf32r(v.x); v.y = tf32r(v.y); v.z = tf32r(v.z); v.w = tf32r(v.w);
        reinterpret_cast<float4*>(g_xcvt)[i] = v;
    } else if (i < CVT_JOBS) {
        int j = i - NX4;
        int w = j >> 12;
        int o = j & 4095;
        const float4* src = (w == 0) ? w0 : (w == 1) ? w1 : (w == 2) ? w2
                          : (w == 3) ? w3 : (w == 4) ? w4 : w5;
        float4 v = src[o];
        v.x = tf32r(v.x); v.y = tf32r(v.y); v.z = tf32r(v.z); v.w = tf32r(v.w);
        reinterpret_cast<float4*>(g_wcvt)[j] = v;
    } else {
        int e = i - CVT_JOBS;
        if (e < NEE) {
            int dst = (e < NE) ? ei[NE + e] : (e - NE);
            atomicAdd(&g_cnt[dst], 1);
        }
    }
}

// ============================ CSR build ============================

__global__ void scan1_kernel() {
    __shared__ int sh[1024];
    int tid = threadIdx.x;
    int base = blockIdx.x * 2048;
    int i0 = base + 2 * tid;
    int a = (i0     < NN) ? g_cnt[i0]     : 0;
    int b = (i0 + 1 < NN) ? g_cnt[i0 + 1] : 0;
    int pair = a + b;
    sh[tid] = pair;
    __syncthreads();
    #pragma unroll
    for (int o = 1; o < 1024; o <<= 1) {
        int t = (tid >= o) ? sh[tid - o] : 0;
        __syncthreads();
        sh[tid] += t;
        __syncthreads();
    }
    int excl = sh[tid] - pair;
    if (i0     < NN) g_rowptr[i0]     = excl;
    if (i0 + 1 < NN) g_rowptr[i0 + 1] = excl + a;
    if (tid == 1023) g_bsum[blockIdx.x] = sh[1023];
}

__global__ void scan23_kernel() {
    __shared__ int sboff[32];
    int tid = threadIdx.x;
    if (tid < 32) {
        int v = (tid < NB) ? g_bsum[tid] : 0;
        int orig = v;
        #pragma unroll
        for (int o = 1; o < 32; o <<= 1) {
            int t = __shfl_up_sync(0xFFFFFFFFu, v, o);
            if (tid >= o) v += t;
        }
        sboff[tid] = v - orig;
        if (tid == NB - 1) g_rowptr[NN] = v;
    }
    __syncthreads();
    int i = blockIdx.x * blockDim.x + tid;
    if (i < NN) {
        int r = g_rowptr[i] + sboff[i >> 11];
        g_rowptr[i] = r;
        g_off[i]    = r;
        g_cnt[i]    = 0;
    }
}

__global__ void scatter_kernel(const int* __restrict__ ei) {
    int e = blockIdx.x * blockDim.x + threadIdx.x;
    if (e >= NEE) return;
    int src, dst;
    if (e < NE) { src = ei[e]; dst = ei[NE + e]; }
    else        { src = e - NE; dst = e - NE; }
    int pos = atomicAdd(&g_off[dst], 1);
    g_csrc[pos] = src;
}

// ==================== fused triple GEMM: cp.async 3-stage pipelined ====================

#define GM 128
#define GK 32
#define XS_STR 36
#define WS_STR 136
#define STAGE_F (GM * XS_STR + GK * WS_STR)   // 8960 floats
#define STAGE_B (STAGE_F * 4)                 // 35840 bytes
#define GSMEM   (3 * STAGE_B)                 // 107520 bytes

__device__ __forceinline__ void mma_tf32(float* d, const unsigned* a, const unsigned* b) {
    asm volatile(
        "mma.sync.aligned.m16n8k8.row.col.f32.tf32.tf32.f32 "
        "{%0,%1,%2,%3}, {%4,%5,%6,%7}, {%8,%9}, {%0,%1,%2,%3};"
        : "+f"(d[0]), "+f"(d[1]), "+f"(d[2]), "+f"(d[3])
        : "r"(a[0]), "r"(a[1]), "r"(a[2]), "r"(a[3]), "r"(b[0]), "r"(b[1]));
}

__device__ __forceinline__ void cp16(uint32_t dst, const float* src, int sz) {
    asm volatile("cp.async.cg.shared.global [%0], [%1], 16, %2;\n"
                 :: "r"(dst), "l"(src), "r"(sz));
}

__device__ __forceinline__ void issue_tile(
    const float* __restrict__ x, const float* __restrict__ W,
    int m0, int kc, uint32_t sbase, int tid) {
    #pragma unroll
    for (int t = 0; t < 4; t++) {
        int f   = tid + t * 256;
        int row = f >> 3;
        int c4  = f & 7;
        int m   = m0 + row;
        int mc  = (m < NN) ? m : (NN - 1);
        cp16(sbase + (row * XS_STR + c4 * 4) * 4,
             &x[mc * DD + kc + c4 * 4], (m < NN) ? 16 : 0);
    }
    uint32_t wbase = sbase + GM * XS_STR * 4;
    #pragma unroll
    for (int t = 0; t < 4; t++) {
        int f   = tid + t * 256;
        int row = f >> 5;
        int c4  = f & 31;
        cp16(wbase + (row * WS_STR + c4 * 4) * 4,
             &W[(kc + row) * DD + c4 * 4], 16);
    }
    asm volatile("cp.async.commit_group;\n");
}

__global__ void __launch_bounds__(256, 2)
gemm3_kernel(int xsel /*0: g_xcvt, 1: g_h*/, int layer,
             const float* __restrict__ b0, const float* __restrict__ b1,
             const float* __restrict__ b2) {
    const float* x = xsel ? g_h : g_xcvt;
    const float* W = g_wcvt + (layer * 3 + blockIdx.y) * (DD * DD);
    const float* bias;
    float* out;
    if (blockIdx.y == 0)      { bias = b0; out = g_xl; }
    else if (blockIdx.y == 1) { bias = b1; out = g_xr; }
    else                      { bias = b2; out = g_res; }

    extern __shared__ float smem[];
    uint32_t sm0 = (uint32_t)__cvta_generic_to_shared(smem);

    int tid  = threadIdx.x;
    int lane = tid & 31;
    int wid  = tid >> 5;
    int wm   = wid & 3;
    int wn   = wid >> 2;
    int g    = lane >> 2;
    int t4   = lane & 3;
    int m0   = blockIdx.x * GM;

    float acc[2][8][4];
    #pragma unroll
    for (int mt = 0; mt < 2; mt++)
        #pragma unroll
        for (int nt = 0; nt < 8; nt++)
            #pragma unroll
            for (int i = 0; i < 4; i++) acc[mt][nt][i] = 0.f;

    // prologue: stages 0,1
    issue_tile(x, W, m0, 0,  sm0,           tid);
    issue_tile(x, W, m0, GK, sm0 + STAGE_B, tid);

    #pragma unroll
    for (int kci = 0; kci < 4; kci++) {
        if (kci < 2)
            issue_tile(x, W, m0, (kci + 2) * GK,
                       sm0 + ((kci + 2) % 3) * STAGE_B, tid);
        if (kci <= 1)      { asm volatile("cp.async.wait_group 2;\n"); }
        else if (kci == 2) { asm volatile("cp.async.wait_group 1;\n"); }
        else               { asm volatile("cp.async.wait_group 0;\n"); }
        __syncthreads();

        const float* xs = smem + (kci % 3) * STAGE_F;
        const float* ws = xs + GM * XS_STR;

        #pragma unroll
        for (int ks = 0; ks < GK; ks += 8) {
            unsigned A[2][4];
            #pragma unroll
            for (int mt = 0; mt < 2; mt++) {
                int r0 = wm * 32 + mt * 16;
                A[mt][0] = __float_as_uint(xs[(r0 + g    ) * XS_STR + ks + t4    ]);
                A[mt][1] = __float_as_uint(xs[(r0 + 8 + g) * XS_STR + ks + t4    ]);
                A[mt][2] = __float_as_uint(xs[(r0 + g    ) * XS_STR + ks + t4 + 4]);
                A[mt][3] = __float_as_uint(xs[(r0 + 8 + g) * XS_STR + ks + t4 + 4]);
            }
            unsigned B[8][2];
            #pragma unroll
            for (int nt = 0; nt < 8; nt++) {
                int c0 = wn * 64 + nt * 8 + g;
                B[nt][0] = __float_as_uint(ws[(ks + t4    ) * WS_STR + c0]);
                B[nt][1] = __float_as_uint(ws[(ks + t4 + 4) * WS_STR + c0]);
            }
            #pragma unroll
            for (int mt = 0; mt < 2; mt++)
                #pragma unroll
                for (int nt = 0; nt < 8; nt++)
                    mma_tf32(acc[mt][nt], A[mt], B[nt]);
        }
        __syncthreads();
    }

    #pragma unroll
    for (int mt = 0; mt < 2; mt++) {
        #pragma unroll
        for (int nt = 0; nt < 8; nt++) {
            int r = m0 + wm * 32 + mt * 16 + g;
            int c = wn * 64 + nt * 8 + t4 * 2;
            float bv0 = bias[c], bv1 = bias[c + 1];
            if (r < NN) {
                out[r * DD + c]     = acc[mt][nt][0] + bv0;
                out[r * DD + c + 1] = acc[mt][nt][1] + bv1;
            }
            if (r + 8 < NN) {
                out[(r + 8) * DD + c]     = acc[mt][nt][2] + bv0;
                out[(r + 8) * DD + c + 1] = acc[mt][nt][3] + bv1;
            }
        }
    }
}

// ================= fused edge kernel: group-of-8 reduction, unroll-4 + index prefetch ==

__device__ __forceinline__ float lrelu(float t) {
    return t > 0.f ? t : 0.2f * t;
}

__global__ void edge_kernel(const float* __restrict__ att,
                            const float* __restrict__ gam,
                            const float* __restrict__ bet,
                            float* outp /* null -> g_h (tf32-rounded) */) {
    float* out = outp ? outp : g_h;
    int d = (blockIdx.x * blockDim.x + threadIdx.x) >> 5;
    int lane = threadIdx.x & 31;
    if (d >= NN) return;

    float4 xr = *reinterpret_cast<const float4*>(&g_xr[d * DD + lane * 4]);
    float4 at = __ldg(reinterpret_cast<const float4*>(&att[lane * 4]));

    float s = 0.f;
    float a0 = 0.f, a1 = 0.f, a2 = 0.f, a3 = 0.f;

    int e0 = g_rowptr[d], e1 = g_rowptr[d + 1];
    int e = e0;

    int i0, i1, i2, i3;
    bool have = (e + 4 <= e1);
    if (have) {
        i0 = __ldg(&g_csrc[e]);
        i1 = __ldg(&g_csrc[e + 1]);
        i2 = __ldg(&g_csrc[e + 2]);
        i3 = __ldg(&g_csrc[e + 3]);
    }
    while (have) {
        // prefetch next iteration's indices before the dependent gathers
        bool hn = (e + 8 <= e1);
        int n0, n1, n2, n3;
        if (hn) {
            n0 = __ldg(&g_csrc[e + 4]);
            n1 = __ldg(&g_csrc[e + 5]);
            n2 = __ldg(&g_csrc[e + 6]);
            n3 = __ldg(&g_csrc[e + 7]);
        }

        float4 v0 = __ldg(reinterpret_cast<const float4*>(&g_xl[i0 * DD + lane * 4]));
        float4 v1 = __ldg(reinterpret_cast<const float4*>(&g_xl[i1 * DD + lane * 4]));
        float4 v2 = __ldg(reinterpret_cast<const float4*>(&g_xl[i2 * DD + lane * 4]));
        float4 v3 = __ldg(reinterpret_cast<const float4*>(&g_xl[i3 * DD + lane * 4]));

        float p0 = lrelu(v0.x + xr.x) * at.x;
        p0 = fmaf(lrelu(v0.y + xr.y), at.y, p0);
        p0 = fmaf(lrelu(v0.z + xr.z), at.z, p0);
        p0 = fmaf(lrelu(v0.w + xr.w), at.w, p0);
        float p1 = lrelu(v1.x + xr.x) * at.x;
        p1 = fmaf(lrelu(v1.y + xr.y), at.y, p1);
        p1 = fmaf(lrelu(v1.z + xr.z), at.z, p1);
        p1 = fmaf(lrelu(v1.w + xr.w), at.w, p1);
        float p2 = lrelu(v2.x + xr.x) * at.x;
        p2 = fmaf(lrelu(v2.y + xr.y), at.y, p2);
        p2 = fmaf(lrelu(v2.z + xr.z), at.z, p2);
        p2 = fmaf(lrelu(v2.w + xr.w), at.w, p2);
        float p3 = lrelu(v3.x + xr.x) * at.x;
        p3 = fmaf(lrelu(v3.y + xr.y), at.y, p3);
        p3 = fmaf(lrelu(v3.z + xr.z), at.z, p3);
        p3 = fmaf(lrelu(v3.w + xr.w), at.w, p3);

        #pragma unroll
        for (int o = 4; o > 0; o >>= 1) {
            p0 += __shfl_xor_sync(0xFFFFFFFFu, p0, o);
            p1 += __shfl_xor_sync(0xFFFFFFFFu, p1, o);
            p2 += __shfl_xor_sync(0xFFFFFFFFu, p2, o);
            p3 += __shfl_xor_sync(0xFFFFFFFFu, p3, o);
        }
        float c0 = __expf(p0), c1 = __expf(p1), c2 = __expf(p2), c3 = __expf(p3);
        s += (c0 + c1) + (c2 + c3);
        a0 = fmaf(c0, v0.x, fmaf(c1, v1.x, fmaf(c2, v2.x, fmaf(c3, v3.x, a0))));
        a1 = fmaf(c0, v0.y, fmaf(c1, v1.y, fmaf(c2, v2.y, fmaf(c3, v3.y, a1))));
        a2 = fmaf(c0, v0.z, fmaf(c1, v1.z, fmaf(c2, v2.z, fmaf(c3, v3.z, a2))));
        a3 = fmaf(c0, v0.w, fmaf(c1, v1.w, fmaf(c2, v2.w, fmaf(c3, v3.w, a3))));

        i0 = n0; i1 = n1; i2 = n2; i3 = n3;
        e += 4;
        have = hn;
    }
    for (; e < e1; e++) {
        int j0 = __ldg(&g_csrc[e]);
        float4 v0 = __ldg(reinterpret_cast<const float4*>(&g_xl[j0 * DD + lane * 4]));
        float p0 = lrelu(v0.x + xr.x) * at.x;
        p0 = fmaf(lrelu(v0.y + xr.y), at.y, p0);
        p0 = fmaf(lrelu(v0.z + xr.z), at.z, p0);
        p0 = fmaf(lrelu(v0.w + xr.w), at.w, p0);
        #pragma unroll
        for (int o = 4; o > 0; o >>= 1)
            p0 += __shfl_xor_sync(0xFFFFFFFFu, p0, o);
        float c0 = __expf(p0);
        s += c0;
        a0 = fmaf(c0, v0.x, a0);
        a1 = fmaf(c0, v0.y, a1);
        a2 = fmaf(c0, v0.z, a2);
        a3 = fmaf(c0, v0.w, a3);
    }

    // residual + bias, then LayerNorm + ReLU
    float4 rsd = *reinterpret_cast<const float4*>(&g_res[d * DD + lane * 4]);
    float inv = 1.f / s;
    float o0 = a0 * inv + rsd.x;
    float o1 = a1 * inv + rsd.y;
    float o2 = a2 * inv + rsd.z;
    float o3 = a3 * inv + rsd.w;

    float sum = o0 + o1 + o2 + o3;
    #pragma unroll
    for (int off = 16; off > 0; off >>= 1)
        sum += __shfl_xor_sync(0xFFFFFFFFu, sum, off);
    float mu = sum * (1.f / 128.f);

    float var = (o0 - mu) * (o0 - mu) + (o1 - mu) * (o1 - mu)
              + (o2 - mu) * (o2 - mu) + (o3 - mu) * (o3 - mu);
    #pragma unroll
    for (int off = 16; off > 0; off >>= 1)
        var += __shfl_xor_sync(0xFFFFFFFFu, var, off);
    var *= (1.f / 128.f);
    float rs = rsqrtf(var + 1e-5f);

    float4 gm = __ldg(reinterpret_cast<const float4*>(&gam[lane * 4]));
    float4 bt = __ldg(reinterpret_cast<const float4*>(&bet[lane * 4]));
    float4 y;
    y.x = fmaxf((o0 - mu) * rs * gm.x + bt.x, 0.f);
    y.y = fmaxf((o1 - mu) * rs * gm.y + bt.y, 0.f);
    y.z = fmaxf((o2 - mu) * rs * gm.z + bt.z, 0.f);
    y.w = fmaxf((o3 - mu) * rs * gm.w + bt.w, 0.f);
    if (!outp) {
        y.x = tf32r(y.x); y.y = tf32r(y.y); y.z = tf32r(y.z); y.w = tf32r(y.w);
    }
    *reinterpret_cast<float4*>(&out[d * DD + lane * 4]) = y;
}

// ============================ launch ============================

extern "C" void kernel_launch(void* const* d_in, const int* in_sizes, int n_in,
                              void* d_out, int out_size) {
    const float* x     = (const float*)d_in[0];
    const int*   ei    = (const int*)  d_in[1];
    const float* Wl0   = (const float*)d_in[2];
    const float* bl0   = (const float*)d_in[3];
    const float* Wr0   = (const float*)d_in[4];
    const float* br0   = (const float*)d_in[5];
    const float* att0  = (const float*)d_in[6];
    const float* Wres0 = (const float*)d_in[7];
    const float* bias0 = (const float*)d_in[8];
    const float* g0    = (const float*)d_in[9];
    const float* be0   = (const float*)d_in[10];
    const float* Wl1   = (const float*)d_in[11];
    const float* bl1   = (const float*)d_in[12];
    const float* Wr1   = (const float*)d_in[13];
    const float* br1   = (const float*)d_in[14];
    const float* att1  = (const float*)d_in[15];
    const float* Wres1 = (const float*)d_in[16];
    const float* bias1 = (const float*)d_in[17];
    const float* g1    = (const float*)d_in[18];
    const float* be1   = (const float*)d_in[19];
    float* out = (float*)d_out;

    cudaFuncSetAttribute(gemm3_kernel,
                         cudaFuncAttributeMaxDynamicSharedMemorySize, GSMEM);

    // fused convert + histogram (independent work, concurrent blocks)
    int fj = CVT_JOBS + NEE;
    cvt_hist_kernel<<<(fj + 255) / 256, 256>>>(
        (const float4*)x,
        (const float4*)Wl0, (const float4*)Wr0, (const float4*)Wres0,
        (const float4*)Wl1, (const float4*)Wr1, (const float4*)Wres1, ei);

    scan1_kernel<<<NB, 1024>>>();
    scan23_kernel<<<(NN + 255) / 256, 256>>>();
    scatter_kernel<<<(NEE + 255) / 256, 256>>>(ei);

    dim3 gb((NN + GM - 1) / GM, 3);
    int eb = NN / 8;

    gemm3_kernel<<<gb, 256, GSMEM>>>(0, 0, bl0, br0, bias0);
    edge_kernel<<<eb, 256>>>(att0, g0, be0, nullptr);

    gemm3_kernel<<<gb, 256, GSMEM>>>(1, 1, bl1, br1, bias1);
    edge_kernel<<<eb, 256>>>(att1, g1, be1, out);
}

// round 16
// speedup vs baseline: 1.0646x; 1.0646x over previous
#include <cuda_runtime.h>
#include <math_constants.h>
#include <cstdint>

#define NN 50000
#define NE 800000
#define NEE 850000          // NE + NN self loops
#define DD 128
#define HH 4
#define NB 25               // scan blocks (2048 elems each)

// ---- scratch (device globals; no allocations allowed) ----
__device__ float g_xl[NN * DD];
__device__ float g_xr[NN * DD];
__device__ float g_res[NN * DD];
__device__ float g_h[NN * DD];       // tf32-rounded at write (feeds gemm only)
__device__ float g_xcvt[NN * DD];    // tf32-rounded copy of external x
__device__ float g_wcvt[6 * DD * DD];// tf32-rounded weights
__device__ int   g_rowptr[NN + 1];
__device__ int   g_cnt[NN];          // zero at module load; re-zeroed by scan23
__device__ int   g_off[NN];
__device__ int   g_csrc[NEE];
__device__ int   g_bsum[32];

__device__ __forceinline__ unsigned f2tf32(float x) {
    unsigned u;
    asm("cvt.rna.tf32.f32 %0, %1;" : "=r"(u) : "f"(x));
    return u;
}
__device__ __forceinline__ float tf32r(float x) {
    return __uint_as_float(f2tf32(x));
}

// ============ fused: tf32 pre-convert (x + weights) AND dst histogram ============
#define NX4 (NN * DD / 4)        // 1,600,000 float4
#define NW4 (6 * DD * DD / 4)    // 24,576 float4
#define CVT_JOBS (NX4 + NW4)

__global__ void cvt_hist_kernel(const float4* __restrict__ x,
                                const float4* __restrict__ w0, const float4* __restrict__ w1,
                                const float4* __restrict__ w2, const float4* __restrict__ w3,
                                const float4* __restrict__ w4, const float4* __restrict__ w5,
                                const int* __restrict__ ei) {
    int i = blockIdx.x * blockDim.x + threadIdx.x;
    if (i < NX4) {
        float4 v = x[i];
        v.x = tf32r(v.x); v.y = tf32r(v.y); v.z = tf32r(v.z); v.w = tf32r(v.w);
        reinterpret_cast<float4*>(g_xcvt)[i] = v;
    } else if (i < CVT_JOBS) {
        int j = i - NX4;
        int w = j >> 12;
        int o = j & 4095;
        const float4* src = (w == 0) ? w0 : (w == 1) ? w1 : (w == 2) ? w2
                          : (w == 3) ? w3 : (w == 4) ? w4 : w5;
        float4 v = src[o];
        v.x = tf32r(v.x); v.y = tf32r(v.y); v.z = tf32r(v.z); v.w = tf32r(v.w);
        reinterpret_cast<float4*>(g_wcvt)[j] = v;
    } else {
        int e = i - CVT_JOBS;
        if (e < NEE) {
            int dst = (e < NE) ? ei[NE + e] : (e - NE);
            atomicAdd(&g_cnt[dst], 1);
        }
    }
}

// ============================ CSR build ============================

__global__ void scan1_kernel() {
    __shared__ int sh[1024];
    int tid = threadIdx.x;
    int base = blockIdx.x * 2048;
    int i0 = base + 2 * tid;
    int a = (i0     < NN) ? g_cnt[i0]     : 0;
    int b = (i0 + 1 < NN) ? g_cnt[i0 + 1] : 0;
    int pair = a + b;
    sh[tid] = pair;
    __syncthreads();
    #pragma unroll
    for (int o = 1; o < 1024; o <<= 1) {
        int t = (tid >= o) ? sh[tid - o] : 0;
        __syncthreads();
        sh[tid] += t;
        __syncthreads();
    }
    int excl = sh[tid] - pair;
    if (i0     < NN) g_rowptr[i0]     = excl;
    if (i0 + 1 < NN) g_rowptr[i0 + 1] = excl + a;
    if (tid == 1023) g_bsum[blockIdx.x] = sh[1023];
}

__global__ void scan23_kernel() {
    __shared__ int sboff[32];
    int tid = threadIdx.x;
    if (tid < 32) {
        int v = (tid < NB) ? g_bsum[tid] : 0;
        int orig = v;
        #pragma unroll
        for (int o = 1; o < 32; o <<= 1) {
            int t = __shfl_up_sync(0xFFFFFFFFu, v, o);
            if (tid >= o) v += t;
        }
        sboff[tid] = v - orig;
        if (tid == NB - 1) g_rowptr[NN] = v;
    }
    __syncthreads();
    int i = blockIdx.x * blockDim.x + tid;
    if (i < NN) {
        int r = g_rowptr[i] + sboff[i >> 11];
        g_rowptr[i] = r;
        g_off[i]    = r;
        g_cnt[i]    = 0;
    }
}

__global__ void scatter_kernel(const int* __restrict__ ei) {
    int e = blockIdx.x * blockDim.x + threadIdx.x;
    if (e >= NEE) return;
    int src, dst;
    if (e < NE) { src = ei[e]; dst = ei[NE + e]; }
    else        { src = e - NE; dst = e - NE; }
    int pos = atomicAdd(&g_off[dst], 1);
    g_csrc[pos] = src;
}

// ==================== fused triple GEMM: cp.async 2-stage (R14-proven) ====================

#define GM 128
#define GK 32
#define XS_STR 36
#define WS_STR 136
#define STAGE_F (GM * XS_STR + GK * WS_STR)   // 8960 floats
#define STAGE_B (STAGE_F * 4)                 // 35840 bytes
#define GSMEM   (2 * STAGE_B)                 // 71680 bytes

__device__ __forceinline__ void mma_tf32(float* d, const unsigned* a, const unsigned* b) {
    asm volatile(
        "mma.sync.aligned.m16n8k8.row.col.f32.tf32.tf32.f32 "
        "{%0,%1,%2,%3}, {%4,%5,%6,%7}, {%8,%9}, {%0,%1,%2,%3};"
        : "+f"(d[0]), "+f"(d[1]), "+f"(d[2]), "+f"(d[3])
        : "r"(a[0]), "r"(a[1]), "r"(a[2]), "r"(a[3]), "r"(b[0]), "r"(b[1]));
}

__device__ __forceinline__ void cp16(uint32_t dst, const float* src, int sz) {
    asm volatile("cp.async.cg.shared.global [%0], [%1], 16, %2;\n"
                 :: "r"(dst), "l"(src), "r"(sz));
}

__device__ __forceinline__ void issue_tile(
    const float* __restrict__ x, const float* __restrict__ W,
    int m0, int kc, uint32_t sbase, int tid) {
    #pragma unroll
    for (int t = 0; t < 4; t++) {
        int f   = tid + t * 256;
        int row = f >> 3;
        int c4  = f & 7;
        int m   = m0 + row;
        int mc  = (m < NN) ? m : (NN - 1);
        cp16(sbase + (row * XS_STR + c4 * 4) * 4,
             &x[mc * DD + kc + c4 * 4], (m < NN) ? 16 : 0);
    }
    uint32_t wbase = sbase + GM * XS_STR * 4;
    #pragma unroll
    for (int t = 0; t < 4; t++) {
        int f   = tid + t * 256;
        int row = f >> 5;
        int c4  = f & 31;
        cp16(wbase + (row * WS_STR + c4 * 4) * 4,
             &W[(kc + row) * DD + c4 * 4], 16);
    }
    asm volatile("cp.async.commit_group;\n");
}

__global__ void __launch_bounds__(256, 2)
gemm3_kernel(int xsel /*0: g_xcvt, 1: g_h*/, int layer,
             const float* __restrict__ b0, const float* __restrict__ b1,
             const float* __restrict__ b2) {
    const float* x = xsel ? g_h : g_xcvt;
    const float* W = g_wcvt + (layer * 3 + blockIdx.y) * (DD * DD);
    const float* bias;
    float* out;
    if (blockIdx.y == 0)      { bias = b0; out = g_xl; }
    else if (blockIdx.y == 1) { bias = b1; out = g_xr; }
    else                      { bias = b2; out = g_res; }

    extern __shared__ float smem[];
    uint32_t sm0 = (uint32_t)__cvta_generic_to_shared(smem);

    int tid  = threadIdx.x;
    int lane = tid & 31;
    int wid  = tid >> 5;
    int wm   = wid & 3;
    int wn   = wid >> 2;
    int g    = lane >> 2;
    int t4   = lane & 3;
    int m0   = blockIdx.x * GM;

    float acc[2][8][4];
    #pragma unroll
    for (int mt = 0; mt < 2; mt++)
        #pragma unroll
        for (int nt = 0; nt < 8; nt++)
            #pragma unroll
            for (int i = 0; i < 4; i++) acc[mt][nt][i] = 0.f;

    // prologue: stage 0
    issue_tile(x, W, m0, 0, sm0, tid);

    #pragma unroll
    for (int kci = 0; kci < 4; kci++) {
        if (kci < 3)
            issue_tile(x, W, m0, (kci + 1) * GK, sm0 + ((kci + 1) & 1) * STAGE_B, tid);
        if (kci < 3) { asm volatile("cp.async.wait_group 1;\n"); }
        else         { asm volatile("cp.async.wait_group 0;\n"); }
        __syncthreads();

        const float* xs = smem + (kci & 1) * STAGE_F;
        const float* ws = xs + GM * XS_STR;

        #pragma unroll
        for (int ks = 0; ks < GK; ks += 8) {
            unsigned A[2][4];
            #pragma unroll
            for (int mt = 0; mt < 2; mt++) {
                int r0 = wm * 32 + mt * 16;
                A[mt][0] = __float_as_uint(xs[(r0 + g    ) * XS_STR + ks + t4    ]);
                A[mt][1] = __float_as_uint(xs[(r0 + 8 + g) * XS_STR + ks + t4    ]);
                A[mt][2] = __float_as_uint(xs[(r0 + g    ) * XS_STR + ks + t4 + 4]);
                A[mt][3] = __float_as_uint(xs[(r0 + 8 + g) * XS_STR + ks + t4 + 4]);
            }
            unsigned B[8][2];
            #pragma unroll
            for (int nt = 0; nt < 8; nt++) {
                int c0 = wn * 64 + nt * 8 + g;
                B[nt][0] = __float_as_uint(ws[(ks + t4    ) * WS_STR + c0]);
                B[nt][1] = __float_as_uint(ws[(ks + t4 + 4) * WS_STR + c0]);
            }
            #pragma unroll
            for (int mt = 0; mt < 2; mt++)
                #pragma unroll
                for (int nt = 0; nt < 8; nt++)
                    mma_tf32(acc[mt][nt], A[mt], B[nt]);
        }
        __syncthreads();
    }

    #pragma unroll
    for (int mt = 0; mt < 2; mt++) {
        #pragma unroll
        for (int nt = 0; nt < 8; nt++) {
            int r = m0 + wm * 32 + mt * 16 + g;
            int c = wn * 64 + nt * 8 + t4 * 2;
            float bv0 = bias[c], bv1 = bias[c + 1];
            if (r < NN) {
                out[r * DD + c]     = acc[mt][nt][0] + bv0;
                out[r * DD + c + 1] = acc[mt][nt][1] + bv1;
            }
            if (r + 8 < NN) {
                out[(r + 8) * DD + c]     = acc[mt][nt][2] + bv0;
                out[(r + 8) * DD + c + 1] = acc[mt][nt][3] + bv1;
            }
        }
    }
}

// ================= fused edge kernel: group-of-8 score reduction, unroll-4 (R14) ==

__device__ __forceinline__ float lrelu(float t) {
    return t > 0.f ? t : 0.2f * t;
}

__global__ void edge_kernel(const float* __restrict__ att,
                            const float* __restrict__ gam,
                            const float* __restrict__ bet,
                            float* outp /* null -> g_h (tf32-rounded) */) {
    float* out = outp ? outp : g_h;
    int d = (blockIdx.x * blockDim.x + threadIdx.x) >> 5;
    int lane = threadIdx.x & 31;
    if (d >= NN) return;

    float4 xr = *reinterpret_cast<const float4*>(&g_xr[d * DD + lane * 4]);
    float4 at = __ldg(reinterpret_cast<const float4*>(&att[lane * 4]));

    float s = 0.f;
    float a0 = 0.f, a1 = 0.f, a2 = 0.f, a3 = 0.f;

    int e0 = g_rowptr[d], e1 = g_rowptr[d + 1];
    int e = e0;

    for (; e + 4 <= e1; e += 4) {
        int i0 = __ldg(&g_csrc[e]);
        int i1 = __ldg(&g_csrc[e + 1]);
        int i2 = __ldg(&g_csrc[e + 2]);
        int i3 = __ldg(&g_csrc[e + 3]);
        float4 v0 = __ldg(reinterpret_cast<const float4*>(&g_xl[i0 * DD + lane * 4]));
        float4 v1 = __ldg(reinterpret_cast<const float4*>(&g_xl[i1 * DD + lane * 4]));
        float4 v2 = __ldg(reinterpret_cast<const float4*>(&g_xl[i2 * DD + lane * 4]));
        float4 v3 = __ldg(reinterpret_cast<const float4*>(&g_xl[i3 * DD + lane * 4]));

        float p0 = lrelu(v0.x + xr.x) * at.x;
        p0 = fmaf(lrelu(v0.y + xr.y), at.y, p0);
        p0 = fmaf(lrelu(v0.z + xr.z), at.z, p0);
        p0 = fmaf(lrelu(v0.w + xr.w), at.w, p0);
        float p1 = lrelu(v1.x + xr.x) * at.x;
        p1 = fmaf(lrelu(v1.y + xr.y), at.y, p1);
        p1 = fmaf(lrelu(v1.z + xr.z), at.z, p1);
        p1 = fmaf(lrelu(v1.w + xr.w), at.w, p1);
        float p2 = lrelu(v2.x + xr.x) * at.x;
        p2 = fmaf(lrelu(v2.y + xr.y), at.y, p2);
        p2 = fmaf(lrelu(v2.z + xr.z), at.z, p2);
        p2 = fmaf(lrelu(v2.w + xr.w), at.w, p2);
        float p3 = lrelu(v3.x + xr.x) * at.x;
        p3 = fmaf(lrelu(v3.y + xr.y), at.y, p3);
        p3 = fmaf(lrelu(v3.z + xr.z), at.z, p3);
        p3 = fmaf(lrelu(v3.w + xr.w), at.w, p3);

        #pragma unroll
        for (int o = 4; o > 0; o >>= 1) {
            p0 += __shfl_xor_sync(0xFFFFFFFFu, p0, o);
            p1 += __shfl_xor_sync(0xFFFFFFFFu, p1, o);
            p2 += __shfl_xor_sync(0xFFFFFFFFu, p2, o);
            p3 += __shfl_xor_sync(0xFFFFFFFFu, p3, o);
        }
        float c0 = __expf(p0), c1 = __expf(p1), c2 = __expf(p2), c3 = __expf(p3);
        s += (c0 + c1) + (c2 + c3);
        a0 = fmaf(c0, v0.x, fmaf(c1, v1.x, fmaf(c2, v2.x, fmaf(c3, v3.x, a0))));
        a1 = fmaf(c0, v0.y, fmaf(c1, v1.y, fmaf(c2, v2.y, fmaf(c3, v3.y, a1))));
        a2 = fmaf(c0, v0.z, fmaf(c1, v1.z, fmaf(c2, v2.z, fmaf(c3, v3.z, a2))));
        a3 = fmaf(c0, v0.w, fmaf(c1, v1.w, fmaf(c2, v2.w, fmaf(c3, v3.w, a3))));
    }
    for (; e < e1; e++) {
        int i0 = __ldg(&g_csrc[e]);
        float4 v0 = __ldg(reinterpret_cast<const float4*>(&g_xl[i0 * DD + lane * 4]));
        float p0 = lrelu(v0.x + xr.x) * at.x;
        p0 = fmaf(lrelu(v0.y + xr.y), at.y, p0);
        p0 = fmaf(lrelu(v0.z + xr.z), at.z, p0);
        p0 = fmaf(lrelu(v0.w + xr.w), at.w, p0);
        #pragma unroll
        for (int o = 4; o > 0; o >>= 1)
            p0 += __shfl_xor_sync(0xFFFFFFFFu, p0, o);
        float c0 = __expf(p0);
        s += c0;
        a0 = fmaf(c0, v0.x, a0);
        a1 = fmaf(c0, v0.y, a1);
        a2 = fmaf(c0, v0.z, a2);
        a3 = fmaf(c0, v0.w, a3);
    }

    // residual + bias, then LayerNorm + ReLU
    float4 rsd = *reinterpret_cast<const float4*>(&g_res[d * DD + lane * 4]);
    float inv = 1.f / s;
    float o0 = a0 * inv + rsd.x;
    float o1 = a1 * inv + rsd.y;
    float o2 = a2 * inv + rsd.z;
    float o3 = a3 * inv + rsd.w;

    float sum = o0 + o1 + o2 + o3;
    #pragma unroll
    for (int off = 16; off > 0; off >>= 1)
        sum += __shfl_xor_sync(0xFFFFFFFFu, sum, off);
    float mu = sum * (1.f / 128.f);

    float var = (o0 - mu) * (o0 - mu) + (o1 - mu) * (o1 - mu)
              + (o2 - mu) * (o2 - mu) + (o3 - mu) * (o3 - mu);
    #pragma unroll
    for (int off = 16; off > 0; off >>= 1)
        var += __shfl_xor_sync(0xFFFFFFFFu, var, off);
    var *= (1.f / 128.f);
    float rs = rsqrtf(var + 1e-5f);

    float4 gm = __ldg(reinterpret_cast<const float4*>(&gam[lane * 4]));
    float4 bt = __ldg(reinterpret_cast<const float4*>(&bet[lane * 4]));
    float4 y;
    y.x = fmaxf((o0 - mu) * rs * gm.x + bt.x, 0.f);
    y.y = fmaxf((o1 - mu) * rs * gm.y + bt.y, 0.f);
    y.z = fmaxf((o2 - mu) * rs * gm.z + bt.z, 0.f);
    y.w = fmaxf((o3 - mu) * rs * gm.w + bt.w, 0.f);
    if (!outp) {
        y.x = tf32r(y.x); y.y = tf32r(y.y); y.z = tf32r(y.z); y.w = tf32r(y.w);
    }
    *reinterpret_cast<float4*>(&out[d * DD + lane * 4]) = y;
}

// ============================ launch ============================

extern "C" void kernel_launch(void* const* d_in, const int* in_sizes, int n_in,
                              void* d_out, int out_size) {
    const float* x     = (const float*)d_in[0];
    const int*   ei    = (const int*)  d_in[1];
    const float* Wl0   = (const float*)d_in[2];
    const float* bl0   = (const float*)d_in[3];
    const float* Wr0   = (const float*)d_in[4];
    const float* br0   = (const float*)d_in[5];
    const float* att0  = (const float*)d_in[6];
    const float* Wres0 = (const float*)d_in[7];
    const float* bias0 = (const float*)d_in[8];
    const float* g0    = (const float*)d_in[9];
    const float* be0   = (const float*)d_in[10];
    const float* Wl1   = (const float*)d_in[11];
    const float* bl1   = (const float*)d_in[12];
    const float* Wr1   = (const float*)d_in[13];
    const float* br1   = (const float*)d_in[14];
    const float* att1  = (const float*)d_in[15];
    const float* Wres1 = (const float*)d_in[16];
    const float* bias1 = (const float*)d_in[17];
    const float* g1    = (const float*)d_in[18];
    const float* be1   = (const float*)d_in[19];
    float* out = (float*)d_out;

    cudaFuncSetAttribute(gemm3_kernel,
                         cudaFuncAttributeMaxDynamicSharedMemorySize, GSMEM);

    // fused convert + histogram (independent work, concurrent blocks)
    int fj = CVT_JOBS + NEE;
    cvt_hist_kernel<<<(fj + 255) / 256, 256>>>(
        (const float4*)x,
        (const float4*)Wl0, (const float4*)Wr0, (const float4*)Wres0,
        (const float4*)Wl1, (const float4*)Wr1, (const float4*)Wres1, ei);

    scan1_kernel<<<NB, 1024>>>();
    scan23_kernel<<<(NN + 255) / 256, 256>>>();
    scatter_kernel<<<(NEE + 255) / 256, 256>>>(ei);

    dim3 gb((NN + GM - 1) / GM, 3);
    int eb = NN / 8;

    gemm3_kernel<<<gb, 256, GSMEM>>>(0, 0, bl0, br0, bias0);
    edge_kernel<<<eb, 256>>>(att0, g0, be0, nullptr);

    gemm3_kernel<<<gb, 256, GSMEM>>>(1, 1, bl1, br1, bias1);
    edge_kernel<<<eb, 256>>>(att1, g1, be1, out);
}